// round 10
// baseline (speedup 1.0000x reference)
#include <cuda_runtime.h>

#define FULLMASK 0xffffffffu
#define WS 256
#define NT 256
#define JB 4                            // batches per half-warp

// ---- smem layout (float offsets) ----
#define OFF_W1T 0                       // [64][256]  Whh1^T
#define OFF_W2T (64 * WS)               // [128][256] rows 0..63 Wih2^T, 64..127 Whh2^T
#define OFF_SM1 (OFF_W2T + 128 * WS)    // mem1 buf: [8 warps][2 bg][4 j][64 h]
#define OFF_SM2 (OFF_SM1 + 4096)        // mem2 buf: same shape
#define SMEM_FLOATS (OFF_SM2 + 4096)
#define SMEM_BYTES  (SMEM_FLOATS * 4)   // 229376 B

typedef unsigned long long u64;

static __device__ __forceinline__ u64 splat2(float x) {
    u64 d;
    asm("mov.b64 %0, {%1, %1};" : "=l"(d) : "f"(x));
    return d;
}
static __device__ __forceinline__ u64 pack2(float lo, float hi) {
    u64 d;
    asm("mov.b64 %0, {%1, %2};" : "=l"(d) : "f"(lo), "f"(hi));
    return d;
}
static __device__ __forceinline__ float2 unpack2(u64 v) {
    float lo, hi;
    asm("mov.b64 {%0, %1}, %2;" : "=f"(lo), "=f"(hi) : "l"(v));
    return make_float2(lo, hi);
}
static __device__ __forceinline__ u64 fma2(u64 a, u64 b, u64 c) {
    u64 d;
    asm("fma.rn.f32x2 %0, %1, %2, %3;" : "=l"(d) : "l"(a), "l"(b), "l"(c));
    return d;
}

// Fused SLSTM pointwise with shared reciprocals: 5 EX2 + 2 RCP.
static __device__ __forceinline__ void cellpw(float Gi, float Gf, float Gg, float Go,
                                              float& syn, float& mem, float& spk,
                                              float thr) {
    float a = 1.0f + __expf(-Gi);
    float c = 1.0f + __expf(-Gf);
    float b = 1.0f + __expf(-2.0f * Gg);
    float ab = a * b;
    float r = __fdividef(1.0f, ab * c);
    float sn = (ab * syn + c * (2.0f - b)) * r;
    float p = 1.0f + __expf(-Go);
    float q = 1.0f + __expf(-2.0f * sn);
    float s = __fdividef(1.0f, p * q);
    float rst = (mem > thr) ? thr : 0.0f;
    float mn = s * (2.0f - q) - rst;
    syn = sn;
    mem = mn;
    spk = (mn > thr) ? 1.0f : 0.0f;
}

// Matvec with smem-resident source: srcb[j*64 + h] (half-warp uniform address
// -> broadcast, 1 wf per LDS.128 covering 4 h values for batch j).
static __device__ __forceinline__ void gemm_smem(u64 (&acc)[4][JB][2],
                                                 const float* __restrict__ wbase,
                                                 const float* __restrict__ srcb,
                                                 int n0) {
#pragma unroll 2
    for (int h4 = 0; h4 < 16; ++h4) {
        float4 s4[JB];
#pragma unroll
        for (int j = 0; j < JB; ++j)
            s4[j] = *(const float4*)(srcb + j * 64 + h4 * 4);
#pragma unroll
        for (int n = 0; n < 4; ++n) {
            const float* wr = wbase + (h4 * 4 + n) * WS + n0;
            ulonglong2 wg0 = *(const ulonglong2*)(wr);
            ulonglong2 wg1 = *(const ulonglong2*)(wr + 64);
            ulonglong2 wg2 = *(const ulonglong2*)(wr + 128);
            ulonglong2 wg3 = *(const ulonglong2*)(wr + 192);
#pragma unroll
            for (int j = 0; j < JB; ++j) {
                const float* sp = &s4[j].x;
                u64 s = splat2(sp[n]);
                acc[0][j][0] = fma2(s, wg0.x, acc[0][j][0]);
                acc[0][j][1] = fma2(s, wg0.y, acc[0][j][1]);
                acc[1][j][0] = fma2(s, wg1.x, acc[1][j][0]);
                acc[1][j][1] = fma2(s, wg1.y, acc[1][j][1]);
                acc[2][j][0] = fma2(s, wg2.x, acc[2][j][0]);
                acc[2][j][1] = fma2(s, wg2.y, acc[2][j][1]);
                acc[3][j][0] = fma2(s, wg3.x, acc[3][j][0]);
                acc[3][j][1] = fma2(s, wg3.y, acc[3][j][1]);
            }
        }
    }
}

// Matvec with register source broadcast via shfl (spk1 path, as in R4).
static __device__ __forceinline__ void gemm_shfl(u64 (&acc)[4][JB][2],
                                                 const float* __restrict__ wbase,
                                                 const float (&src)[4][JB],
                                                 int srcbase, int n0) {
#pragma unroll 2
    for (int h4 = 0; h4 < 16; ++h4) {
#pragma unroll
        for (int n = 0; n < 4; ++n) {
            const float* wr = wbase + (h4 * 4 + n) * WS + n0;
            ulonglong2 wg0 = *(const ulonglong2*)(wr);
            ulonglong2 wg1 = *(const ulonglong2*)(wr + 64);
            ulonglong2 wg2 = *(const ulonglong2*)(wr + 128);
            ulonglong2 wg3 = *(const ulonglong2*)(wr + 192);
#pragma unroll
            for (int j = 0; j < JB; ++j) {
                u64 s = splat2(__shfl_sync(FULLMASK, src[n][j], srcbase + h4));
                acc[0][j][0] = fma2(s, wg0.x, acc[0][j][0]);
                acc[0][j][1] = fma2(s, wg0.y, acc[0][j][1]);
                acc[1][j][0] = fma2(s, wg1.x, acc[1][j][0]);
                acc[1][j][1] = fma2(s, wg1.y, acc[1][j][1]);
                acc[2][j][0] = fma2(s, wg2.x, acc[2][j][0]);
                acc[2][j][1] = fma2(s, wg2.y, acc[2][j][1]);
                acc[3][j][0] = fma2(s, wg3.x, acc[3][j][0]);
                acc[3][j][1] = fma2(s, wg3.y, acc[3][j][1]);
            }
        }
    }
}

__global__ void __launch_bounds__(NT, 1)
snn_kernel(const float* __restrict__ x,
           const float* __restrict__ Wih1, const float* __restrict__ Whh1,
           const float* __restrict__ bih1, const float* __restrict__ bhh1,
           const float* __restrict__ thr1p,
           const float* __restrict__ Wih2, const float* __restrict__ Whh2,
           const float* __restrict__ bih2, const float* __restrict__ bhh2,
           const float* __restrict__ thr2p,
           const float* __restrict__ Wout, const float* __restrict__ bout,
           float* __restrict__ out) {
    extern __shared__ float sm[];
    const int tid  = threadIdx.x;
    const int lane = tid & 31;
    const int w    = tid >> 5;
    const int hl   = lane & 15;          // position within half-warp
    const int bg   = lane >> 4;          // batch group (0/1)
    const int n0   = hl << 2;            // this lane's 4 neurons
    const int srcbase = bg << 4;
    const int bl   = w * 8 + bg * JB;    // local batch base
    const int cta_b0 = blockIdx.x * 64;

    // ---- stage weights: sm[h*256 + r] = W[r*64 + h] (contiguous STS) ----
    for (int i = tid; i < 64 * 256; i += NT) {
        int r = i & 255, h = i >> 8;
        sm[OFF_W1T + h * WS + r] = Whh1[r * 64 + h];
    }
    for (int i = tid; i < 128 * 256; i += NT) {
        int r = i & 255, h = i >> 8;
        sm[OFF_W2T + h * WS + r] = (h < 64) ? Wih2[r * 64 + h]
                                            : Whh2[r * 64 + (h - 64)];
    }
    // zero this warp's state buffers
    for (int i = lane; i < 512; i += 32) {
        sm[OFF_SM1 + w * 512 + i] = 0.0f;
        sm[OFF_SM2 + w * 512 + i] = 0.0f;
    }
    __syncthreads();

    const float thr1 = thr1p[0], thr2 = thr2p[0];

    // packed per-lane constants: combined biases + Wih1 column, as f32x2 pairs
    u64 cb1u[4][2], cb2u[4][2], wi1u[4][2];
#pragma unroll
    for (int g = 0; g < 4; ++g)
#pragma unroll
        for (int pr = 0; pr < 2; ++pr) {
            int idx = g * 64 + n0 + 2 * pr;
            cb1u[g][pr] = pack2(bih1[idx] + bhh1[idx], bih1[idx + 1] + bhh1[idx + 1]);
            cb2u[g][pr] = pack2(bih2[idx] + bhh2[idx], bih2[idx + 1] + bhh2[idx + 1]);
            wi1u[g][pr] = pack2(Wih1[idx], Wih1[idx + 1]);
        }

    float* m1b = sm + OFF_SM1 + (w * 2 + bg) * 256;   // [j][h]
    float* m2b = sm + OFF_SM2 + (w * 2 + bg) * 256;

    // register-resident state
    float syn1[4][JB], mem1[4][JB], syn2[4][JB], mem2[4][JB], spk1[4][JB];
#pragma unroll
    for (int n = 0; n < 4; ++n)
#pragma unroll
        for (int j = 0; j < JB; ++j)
            syn1[n][j] = mem1[n][j] = syn2[n][j] = mem2[n][j] = spk1[n][j] = 0.0f;

    float oa[JB][2];
#pragma unroll
    for (int j = 0; j < JB; ++j) oa[j][0] = oa[j][1] = 0.0f;

    u64 acc[4][JB][2];

#pragma unroll 1
    for (int t = 0; t < 25; ++t) {
        if (t < 24) {
            // ---- layer 1: gates = Whh1*mem1 + b1 + x*Wih1 ----
#pragma unroll
            for (int g = 0; g < 4; ++g)
#pragma unroll
                for (int j = 0; j < JB; ++j) {
                    acc[g][j][0] = cb1u[g][0];
                    acc[g][j][1] = cb1u[g][1];
                }
            gemm_smem(acc, sm + OFF_W1T, m1b, n0);
#pragma unroll
            for (int j = 0; j < JB; ++j) {
                u64 xs = splat2(__ldg(&x[(cta_b0 + bl + j) * 24 + t]));
#pragma unroll
                for (int g = 0; g < 4; ++g) {
                    acc[g][j][0] = fma2(xs, wi1u[g][0], acc[g][j][0]);
                    acc[g][j][1] = fma2(xs, wi1u[g][1], acc[g][j][1]);
                }
                float2 G[4][2];
#pragma unroll
                for (int g = 0; g < 4; ++g) {
                    G[g][0] = unpack2(acc[g][j][0]);
                    G[g][1] = unpack2(acc[g][j][1]);
                }
#pragma unroll
                for (int n = 0; n < 4; ++n) {
                    float Gi = (n & 1) ? G[0][n >> 1].y : G[0][n >> 1].x;
                    float Gf = (n & 1) ? G[1][n >> 1].y : G[1][n >> 1].x;
                    float Gg = (n & 1) ? G[2][n >> 1].y : G[2][n >> 1].x;
                    float Go = (n & 1) ? G[3][n >> 1].y : G[3][n >> 1].x;
                    cellpw(Gi, Gf, Gg, Go, syn1[n][j], mem1[n][j], spk1[n][j], thr1);
                }
                *(float4*)(m1b + j * 64 + n0) =
                    make_float4(mem1[0][j], mem1[1][j], mem1[2][j], mem1[3][j]);
            }
            __syncwarp();
        }
        // ---- layer 2 ----
#pragma unroll
        for (int g = 0; g < 4; ++g)
#pragma unroll
            for (int j = 0; j < JB; ++j) {
                acc[g][j][0] = cb2u[g][0];
                acc[g][j][1] = cb2u[g][1];
            }
        gemm_smem(acc, sm + OFF_W2T + 64 * WS, m2b, n0);
        if (t < 24) gemm_shfl(acc, sm + OFF_W2T, spk1, srcbase, n0);
        else        gemm_smem(acc, sm + OFF_W2T, m1b, n0);

        float4 wo0 = __ldg((const float4*)(Wout + t * 64 + n0));
        float4 wo1 = __ldg((const float4*)(Wout + 1664 + t * 64 + n0));
        const float* w0a = &wo0.x;
        const float* w1a = &wo1.x;
#pragma unroll
        for (int j = 0; j < JB; ++j) {
            float2 G[4][2];
#pragma unroll
            for (int g = 0; g < 4; ++g) {
                G[g][0] = unpack2(acc[g][j][0]);
                G[g][1] = unpack2(acc[g][j][1]);
            }
#pragma unroll
            for (int n = 0; n < 4; ++n) {
                float Gi = (n & 1) ? G[0][n >> 1].y : G[0][n >> 1].x;
                float Gf = (n & 1) ? G[1][n >> 1].y : G[1][n >> 1].x;
                float Gg = (n & 1) ? G[2][n >> 1].y : G[2][n >> 1].x;
                float Go = (n & 1) ? G[3][n >> 1].y : G[3][n >> 1].x;
                float sp;
                cellpw(Gi, Gf, Gg, Go, syn2[n][j], mem2[n][j], sp, thr2);
                oa[j][0] += sp * w0a[n];
                oa[j][1] += sp * w1a[n];
            }
            *(float4*)(m2b + j * 64 + n0) =
                make_float4(mem2[0][j], mem2[1][j], mem2[2][j], mem2[3][j]);
        }
        __syncwarp();
    }

    // ---- final mem2 contribution (Wout columns 1600..1663) ----
    {
        float4 wm0 = __ldg((const float4*)(Wout + 1600 + n0));
        float4 wm1 = __ldg((const float4*)(Wout + 1664 + 1600 + n0));
        const float* a0 = &wm0.x;
        const float* a1 = &wm1.x;
#pragma unroll
        for (int n = 0; n < 4; ++n)
#pragma unroll
            for (int j = 0; j < JB; ++j) {
                oa[j][0] += mem2[n][j] * a0[n];
                oa[j][1] += mem2[n][j] * a1[n];
            }
    }

    // ---- reduce over the 16 neuron-owner lanes of this half-warp ----
#pragma unroll
    for (int j = 0; j < JB; ++j)
#pragma unroll
        for (int k = 0; k < 2; ++k) {
            float v = oa[j][k];
#pragma unroll
            for (int off = 8; off; off >>= 1)
                v += __shfl_xor_sync(FULLMASK, v, off);
            oa[j][k] = v;
        }

    if (hl < 2 * JB) {
        int j = hl >> 1, k = hl & 1;
        out[(cta_b0 + bl + j) * 2 + k] = oa[j][k] + __ldg(&bout[k]);
    }
}

extern "C" void kernel_launch(void* const* d_in, const int* in_sizes, int n_in,
                              void* d_out, int out_size) {
    const float* x    = (const float*)d_in[0];
    const float* Wih1 = (const float*)d_in[1];
    const float* Whh1 = (const float*)d_in[2];
    const float* bih1 = (const float*)d_in[3];
    const float* bhh1 = (const float*)d_in[4];
    const float* thr1 = (const float*)d_in[5];
    const float* Wih2 = (const float*)d_in[6];
    const float* Whh2 = (const float*)d_in[7];
    const float* bih2 = (const float*)d_in[8];
    const float* bhh2 = (const float*)d_in[9];
    const float* thr2 = (const float*)d_in[10];
    const float* Wout = (const float*)d_in[11];
    const float* bout = (const float*)d_in[12];
    float* out = (float*)d_out;

    int B = in_sizes[0] / 24;  // 65536

    cudaFuncSetAttribute(snn_kernel,
                         cudaFuncAttributeMaxDynamicSharedMemorySize,
                         SMEM_BYTES);

    snn_kernel<<<B / 64, NT, SMEM_BYTES>>>(
        x, Wih1, Whh1, bih1, bhh1, thr1,
        Wih2, Whh2, bih2, bhh2, thr2, Wout, bout, out);
}

// round 11
// speedup vs baseline: 1.6543x; 1.6543x over previous
#include <cuda_runtime.h>

#define FULLMASK 0xffffffffu
#define WS 256
#define NT 256
#define JB 4                            // batches per half-warp

// ---- smem layout (float offsets) ----
#define OFF_W1T  0                      // [64][256]  Whh1^T
#define OFF_W2T  (64 * WS)              // [128][256] rows 0..63 Wih2^T, 64..127 Whh2^T
#define OFF_WIH1 (OFF_W2T + 128 * WS)   // 256
#define OFF_CB1  (OFF_WIH1 + 256)       // 256
#define OFF_CB2  (OFF_CB1 + 256)        // 256
#define OFF_SM1  (OFF_CB2 + 256)        // mem1 buf: [64 batches][64 h]
#define OFF_SM2  (OFF_SM1 + 4096)       // mem2 buf: [64 batches][64 h]
#define SMEM_FLOATS (OFF_SM2 + 4096)
#define SMEM_BYTES  (SMEM_FLOATS * 4)   // 232448 B (== sm_103a per-block max)

typedef unsigned long long u64;

static __device__ __forceinline__ u64 splat2(float x) {
    u64 d;
    asm("mov.b64 %0, {%1, %1};" : "=l"(d) : "f"(x));
    return d;
}
static __device__ __forceinline__ float2 unpack2(u64 v) {
    float lo, hi;
    asm("mov.b64 {%0, %1}, %2;" : "=f"(lo), "=f"(hi) : "l"(v));
    return make_float2(lo, hi);
}
static __device__ __forceinline__ u64 fma2(u64 a, u64 b, u64 c) {
    u64 d;
    asm("fma.rn.f32x2 %0, %1, %2, %3;" : "=l"(d) : "l"(a), "l"(b), "l"(c));
    return d;
}

// Fused SLSTM pointwise with shared reciprocals: 5 EX2 + 2 RCP.
static __device__ __forceinline__ void cellpw(float Gi, float Gf, float Gg, float Go,
                                              float& syn, float& mem, float& spk,
                                              float thr) {
    float a = 1.0f + __expf(-Gi);
    float c = 1.0f + __expf(-Gf);
    float b = 1.0f + __expf(-2.0f * Gg);
    float ab = a * b;
    float r = __fdividef(1.0f, ab * c);
    float sn = (ab * syn + c * (2.0f - b)) * r;
    float p = 1.0f + __expf(-Go);
    float q = 1.0f + __expf(-2.0f * sn);
    float s = __fdividef(1.0f, p * q);
    float rst = (mem > thr) ? thr : 0.0f;
    float mn = s * (2.0f - q) - rst;
    syn = sn;
    mem = mn;
    spk = (mn > thr) ? 1.0f : 0.0f;
}

// Matvec with smem-resident source. srcb[j*64 + h]: uniform address within the
// half-warp -> broadcast LDS.128 (1 wavefront) delivers 4 h-values per j.
static __device__ __forceinline__ void gemm_smem(u64 (&acc)[4][JB][2],
                                                 const float* __restrict__ wbase,
                                                 const float* __restrict__ srcb,
                                                 int n0) {
#pragma unroll 2
    for (int h4 = 0; h4 < 16; ++h4) {
        float4 s0 = *(const float4*)(srcb + 0 * 64 + h4 * 4);
        float4 s1 = *(const float4*)(srcb + 1 * 64 + h4 * 4);
        float4 s2 = *(const float4*)(srcb + 2 * 64 + h4 * 4);
        float4 s3 = *(const float4*)(srcb + 3 * 64 + h4 * 4);
#pragma unroll
        for (int n = 0; n < 4; ++n) {
            const float* wr = wbase + (h4 * 4 + n) * WS + n0;
            ulonglong2 wg0 = *(const ulonglong2*)(wr);
            ulonglong2 wg1 = *(const ulonglong2*)(wr + 64);
            ulonglong2 wg2 = *(const ulonglong2*)(wr + 128);
            ulonglong2 wg3 = *(const ulonglong2*)(wr + 192);
#pragma unroll
            for (int j = 0; j < JB; ++j) {
                float4& sj = (j == 0) ? s0 : (j == 1) ? s1 : (j == 2) ? s2 : s3;
                float sv = (n == 0) ? sj.x : (n == 1) ? sj.y : (n == 2) ? sj.z : sj.w;
                u64 s = splat2(sv);
                acc[0][j][0] = fma2(s, wg0.x, acc[0][j][0]);
                acc[0][j][1] = fma2(s, wg0.y, acc[0][j][1]);
                acc[1][j][0] = fma2(s, wg1.x, acc[1][j][0]);
                acc[1][j][1] = fma2(s, wg1.y, acc[1][j][1]);
                acc[2][j][0] = fma2(s, wg2.x, acc[2][j][0]);
                acc[2][j][1] = fma2(s, wg2.y, acc[2][j][1]);
                acc[3][j][0] = fma2(s, wg3.x, acc[3][j][0]);
                acc[3][j][1] = fma2(s, wg3.y, acc[3][j][1]);
            }
        }
    }
}

// Matvec with register source broadcast via shfl (spk1 path, identical to R4).
static __device__ __forceinline__ void gemm_shfl(u64 (&acc)[4][JB][2],
                                                 const float* __restrict__ wbase,
                                                 const float (&src)[4][JB],
                                                 int srcbase, int n0) {
#pragma unroll 2
    for (int h4 = 0; h4 < 16; ++h4) {
#pragma unroll
        for (int n = 0; n < 4; ++n) {
            const float* wr = wbase + (h4 * 4 + n) * WS + n0;
            ulonglong2 wg0 = *(const ulonglong2*)(wr);
            ulonglong2 wg1 = *(const ulonglong2*)(wr + 64);
            ulonglong2 wg2 = *(const ulonglong2*)(wr + 128);
            ulonglong2 wg3 = *(const ulonglong2*)(wr + 192);
#pragma unroll
            for (int j = 0; j < JB; ++j) {
                u64 s = splat2(__shfl_sync(FULLMASK, src[n][j], srcbase + h4));
                acc[0][j][0] = fma2(s, wg0.x, acc[0][j][0]);
                acc[0][j][1] = fma2(s, wg0.y, acc[0][j][1]);
                acc[1][j][0] = fma2(s, wg1.x, acc[1][j][0]);
                acc[1][j][1] = fma2(s, wg1.y, acc[1][j][1]);
                acc[2][j][0] = fma2(s, wg2.x, acc[2][j][0]);
                acc[2][j][1] = fma2(s, wg2.y, acc[2][j][1]);
                acc[3][j][0] = fma2(s, wg3.x, acc[3][j][0]);
                acc[3][j][1] = fma2(s, wg3.y, acc[3][j][1]);
            }
        }
    }
}

__global__ void __launch_bounds__(NT, 1)
snn_kernel(const float* __restrict__ x,
           const float* __restrict__ Wih1, const float* __restrict__ Whh1,
           const float* __restrict__ bih1, const float* __restrict__ bhh1,
           const float* __restrict__ thr1p,
           const float* __restrict__ Wih2, const float* __restrict__ Whh2,
           const float* __restrict__ bih2, const float* __restrict__ bhh2,
           const float* __restrict__ thr2p,
           const float* __restrict__ Wout, const float* __restrict__ bout,
           float* __restrict__ out) {
    extern __shared__ float sm[];
    const int tid  = threadIdx.x;
    const int lane = tid & 31;
    const int w    = tid >> 5;
    const int hl   = lane & 15;          // position within half-warp
    const int bg   = lane >> 4;          // batch group (0/1)
    const int n0   = hl << 2;            // this lane's 4 neurons
    const int srcbase = bg << 4;
    const int bl   = w * 8 + bg * JB;    // local batch base
    const int cta_b0 = blockIdx.x * 64;

    // ---- stage weights transposed (coalesced LDG, one-time strided STS) ----
    for (int i = tid; i < 256 * 64; i += NT) {
        int r = i >> 6, h = i & 63;
        sm[OFF_W1T + h * WS + r]        = Whh1[i];
        sm[OFF_W2T + h * WS + r]        = Wih2[i];
        sm[OFF_W2T + (64 + h) * WS + r] = Whh2[i];
    }
    if (tid < 256) {
        sm[OFF_WIH1 + tid] = Wih1[tid];
        sm[OFF_CB1 + tid]  = bih1[tid] + bhh1[tid];
        sm[OFF_CB2 + tid]  = bih2[tid] + bhh2[tid];
    }
    // zero state buffers
    for (int i = tid; i < 4096; i += NT) {
        sm[OFF_SM1 + i] = 0.0f;
        sm[OFF_SM2 + i] = 0.0f;
    }
    __syncthreads();

    const float thr1 = thr1p[0], thr2 = thr2p[0];

    float* m1b = sm + OFF_SM1 + bl * 64;   // this half-warp's [j][h]
    float* m2b = sm + OFF_SM2 + bl * 64;

    // register-resident state
    float syn1[4][JB], mem1[4][JB], syn2[4][JB], mem2[4][JB], spk1[4][JB];
#pragma unroll
    for (int n = 0; n < 4; ++n)
#pragma unroll
        for (int j = 0; j < JB; ++j)
            syn1[n][j] = mem1[n][j] = syn2[n][j] = mem2[n][j] = spk1[n][j] = 0.0f;

    float oa[JB][2];
#pragma unroll
    for (int j = 0; j < JB; ++j) oa[j][0] = oa[j][1] = 0.0f;

    u64 acc[4][JB][2];

#pragma unroll 1
    for (int t = 0; t < 25; ++t) {
        if (t < 24) {
            // ---- layer 1: gates = Whh1*mem1 + b1 + x*Wih1 ----
#pragma unroll
            for (int g = 0; g < 4; ++g)
#pragma unroll
                for (int j = 0; j < JB; ++j) acc[g][j][0] = acc[g][j][1] = 0ull;
            gemm_smem(acc, sm + OFF_W1T, m1b, n0);
#pragma unroll
            for (int j = 0; j < JB; ++j) {
                float xv = __ldg(&x[(cta_b0 + bl + j) * 24 + t]);
                float2 G[4][2];
#pragma unroll
                for (int g = 0; g < 4; ++g) {
                    G[g][0] = unpack2(acc[g][j][0]);
                    G[g][1] = unpack2(acc[g][j][1]);
                }
#pragma unroll
                for (int n = 0; n < 4; ++n) {
                    float Gi = ((n & 1) ? G[0][n >> 1].y : G[0][n >> 1].x)
                             + sm[OFF_CB1 + 0 * 64 + n0 + n]
                             + xv * sm[OFF_WIH1 + 0 * 64 + n0 + n];
                    float Gf = ((n & 1) ? G[1][n >> 1].y : G[1][n >> 1].x)
                             + sm[OFF_CB1 + 1 * 64 + n0 + n]
                             + xv * sm[OFF_WIH1 + 1 * 64 + n0 + n];
                    float Gg = ((n & 1) ? G[2][n >> 1].y : G[2][n >> 1].x)
                             + sm[OFF_CB1 + 2 * 64 + n0 + n]
                             + xv * sm[OFF_WIH1 + 2 * 64 + n0 + n];
                    float Go = ((n & 1) ? G[3][n >> 1].y : G[3][n >> 1].x)
                             + sm[OFF_CB1 + 3 * 64 + n0 + n]
                             + xv * sm[OFF_WIH1 + 3 * 64 + n0 + n];
                    cellpw(Gi, Gf, Gg, Go, syn1[n][j], mem1[n][j], spk1[n][j], thr1);
                }
                *(float4*)(m1b + j * 64 + n0) =
                    make_float4(mem1[0][j], mem1[1][j], mem1[2][j], mem1[3][j]);
            }
            __syncwarp();
        }
        // ---- layer 2: input = spk1 (t<24) or mem1 (t==24) ----
#pragma unroll
        for (int g = 0; g < 4; ++g)
#pragma unroll
            for (int j = 0; j < JB; ++j) acc[g][j][0] = acc[g][j][1] = 0ull;
        gemm_smem(acc, sm + OFF_W2T + 64 * WS, m2b, n0);
        if (t < 24) gemm_shfl(acc, sm + OFF_W2T, spk1, srcbase, n0);
        else        gemm_smem(acc, sm + OFF_W2T, m1b, n0);

        float4 wo0 = __ldg((const float4*)(Wout + t * 64 + n0));
        float4 wo1 = __ldg((const float4*)(Wout + 1664 + t * 64 + n0));
#pragma unroll
        for (int j = 0; j < JB; ++j) {
            float2 G[4][2];
#pragma unroll
            for (int g = 0; g < 4; ++g) {
                G[g][0] = unpack2(acc[g][j][0]);
                G[g][1] = unpack2(acc[g][j][1]);
            }
#pragma unroll
            for (int n = 0; n < 4; ++n) {
                float Gi = ((n & 1) ? G[0][n >> 1].y : G[0][n >> 1].x)
                         + sm[OFF_CB2 + 0 * 64 + n0 + n];
                float Gf = ((n & 1) ? G[1][n >> 1].y : G[1][n >> 1].x)
                         + sm[OFF_CB2 + 1 * 64 + n0 + n];
                float Gg = ((n & 1) ? G[2][n >> 1].y : G[2][n >> 1].x)
                         + sm[OFF_CB2 + 2 * 64 + n0 + n];
                float Go = ((n & 1) ? G[3][n >> 1].y : G[3][n >> 1].x)
                         + sm[OFF_CB2 + 3 * 64 + n0 + n];
                float sp;
                cellpw(Gi, Gf, Gg, Go, syn2[n][j], mem2[n][j], sp, thr2);
                float w0n = (n == 0) ? wo0.x : (n == 1) ? wo0.y : (n == 2) ? wo0.z : wo0.w;
                float w1n = (n == 0) ? wo1.x : (n == 1) ? wo1.y : (n == 2) ? wo1.z : wo1.w;
                oa[j][0] += sp * w0n;
                oa[j][1] += sp * w1n;
            }
            *(float4*)(m2b + j * 64 + n0) =
                make_float4(mem2[0][j], mem2[1][j], mem2[2][j], mem2[3][j]);
        }
        __syncwarp();
    }

    // ---- final mem2 contribution (Wout columns 1600..1663) ----
    {
        float4 wm0 = __ldg((const float4*)(Wout + 1600 + n0));
        float4 wm1 = __ldg((const float4*)(Wout + 1664 + 1600 + n0));
#pragma unroll
        for (int n = 0; n < 4; ++n) {
            float a0 = (n == 0) ? wm0.x : (n == 1) ? wm0.y : (n == 2) ? wm0.z : wm0.w;
            float a1 = (n == 0) ? wm1.x : (n == 1) ? wm1.y : (n == 2) ? wm1.z : wm1.w;
#pragma unroll
            for (int j = 0; j < JB; ++j) {
                oa[j][0] += mem2[n][j] * a0;
                oa[j][1] += mem2[n][j] * a1;
            }
        }
    }

    // ---- reduce over the 16 neuron-owner lanes of this half-warp ----
#pragma unroll
    for (int j = 0; j < JB; ++j)
#pragma unroll
        for (int k = 0; k < 2; ++k) {
            float v = oa[j][k];
#pragma unroll
            for (int off = 8; off; off >>= 1)
                v += __shfl_xor_sync(FULLMASK, v, off);
            oa[j][k] = v;
        }

    if (hl < 2 * JB) {
        int j = hl >> 1, k = hl & 1;
        out[(cta_b0 + bl + j) * 2 + k] = oa[j][k] + __ldg(&bout[k]);
    }
}

extern "C" void kernel_launch(void* const* d_in, const int* in_sizes, int n_in,
                              void* d_out, int out_size) {
    const float* x    = (const float*)d_in[0];
    const float* Wih1 = (const float*)d_in[1];
    const float* Whh1 = (const float*)d_in[2];
    const float* bih1 = (const float*)d_in[3];
    const float* bhh1 = (const float*)d_in[4];
    const float* thr1 = (const float*)d_in[5];
    const float* Wih2 = (const float*)d_in[6];
    const float* Whh2 = (const float*)d_in[7];
    const float* bih2 = (const float*)d_in[8];
    const float* bhh2 = (const float*)d_in[9];
    const float* thr2 = (const float*)d_in[10];
    const float* Wout = (const float*)d_in[11];
    const float* bout = (const float*)d_in[12];
    float* out = (float*)d_out;

    int B = in_sizes[0] / 24;  // 65536

    cudaFuncSetAttribute(snn_kernel,
                         cudaFuncAttributeMaxDynamicSharedMemorySize,
                         SMEM_BYTES);

    snn_kernel<<<B / 64, NT, SMEM_BYTES>>>(
        x, Wih1, Whh1, bih1, bhh1, thr1,
        Wih2, Whh2, bih2, bhh2, thr2, Wout, bout, out);
}